// round 10
// baseline (speedup 1.0000x reference)
#include <cuda_runtime.h>

#define TPB 128
#define TILE 128                 // cells per tile (== TPB)
#define NSTAGE 3
#define MAXGRID 1024
#define CH 30
#define SCONST 7.0f
#define TILE_F (TILE * CH)       // floats per tensor per tile (3840)
#define TILE_C16 (TILE_F / 4)    // 16B chunks per tensor per tile (960)

// Persistent-kernel partials + completion counter (no device allocation allowed).
__device__ float g_part[MAXGRID];
__device__ unsigned int g_count;   // zero-init; last block resets to 0 each run

__device__ __forceinline__ void stage_tile(const float* __restrict__ gp,
                                           const float* __restrict__ gt,
                                           unsigned sp_a, unsigned st_a) {
    // full tiles guaranteed by caller (cells % TILE == 0 for this shape;
    // caller skips staging for out-of-range tiles)
    #pragma unroll 3
    for (int i = threadIdx.x; i < TILE_C16; i += TPB) {
        asm volatile("cp.async.cg.shared.global [%0], [%1], 16;"
                     :: "r"(sp_a + i * 16), "l"(gp + i * 4));
        asm volatile("cp.async.cg.shared.global [%0], [%1], 16;"
                     :: "r"(st_a + i * 16), "l"(gt + i * 4));
    }
}

__global__ void __launch_bounds__(TPB, 2)
yolo_loss_kernel(const float* __restrict__ pred,
                 const float* __restrict__ tgt,
                 int cells, int nTiles, float inv_bs,
                 float* __restrict__ out) {
    extern __shared__ float sm[];
    // layout: [stage s] -> pred at s*2*TILE_F, tgt at s*2*TILE_F + TILE_F
    unsigned pA[NSTAGE], tA[NSTAGE];
    float *pS[NSTAGE], *tS[NSTAGE];
    #pragma unroll
    for (int s = 0; s < NSTAGE; ++s) {
        pS[s] = sm + s * 2 * TILE_F;
        tS[s] = pS[s] + TILE_F;
        pA[s] = (unsigned)__cvta_generic_to_shared(pS[s]);
        tA[s] = (unsigned)__cvta_generic_to_shared(tS[s]);
    }

    const int g = gridDim.x;
    float acc = 0.0f;

    // ---- prologue: stage tiles b and b+g (groups 0 and 1) ----
    {
        const int t0 = blockIdx.x;
        if (t0 < nTiles)
            stage_tile(pred + (size_t)t0 * TILE_F, tgt + (size_t)t0 * TILE_F,
                       pA[0], tA[0]);
        asm volatile("cp.async.commit_group;");
        const int t1 = t0 + g;
        if (t1 < nTiles)
            stage_tile(pred + (size_t)t1 * TILE_F, tgt + (size_t)t1 * TILE_F,
                       pA[1], tA[1]);
        asm volatile("cp.async.commit_group;");
    }

    int s = 0;
    for (int tile = blockIdx.x; tile < nTiles; tile += g) {
        // retire all groups except the newest -> tile's data resident
        asm volatile("cp.async.wait_group 1;");
        __syncthreads();   // also proves all warps finished compute(tile-g)

        // refill the buffer freed by compute(tile-g): stage tile+2g
        {
            const int nx = tile + 2 * g;
            const int sn = (s + 2 >= NSTAGE) ? s + 2 - NSTAGE : s + 2;
            if (nx < nTiles)
                stage_tile(pred + (size_t)nx * TILE_F, tgt + (size_t)nx * TILE_F,
                           pA[sn], tA[sn]);
            asm volatile("cp.async.commit_group;");   // always: keep group count
        }

        // ---- compute this tile (one cell per thread) ----
        const int cell = tile * TILE + threadIdx.x;
        if (cell < cells) {
            const float* p = pS[s] + threadIdx.x * CH;
            const float* t = tS[s] + threadIdx.x * CH;

            const float objf   = (t[4] > 0.0f) ? 1.0f : 0.0f;
            const float noobjf = 1.0f - objf;

            // no-object confidence loss (conf channels 4 and 9)
            const float d0 = p[4] - t[4];
            const float d1 = p[9] - t[9];
            const float loss_noobj = noobjf * (d0 * d0 + d1 * d1);

            // class loss (channels 10..29)
            float loss_class = 0.0f;
            #pragma unroll
            for (int k = 10; k < 30; ++k) {
                const float d = p[k] - t[k];
                loss_class += d * d;
            }
            loss_class *= objf;

            // target box 0 -> xyxy (match reference rounding)
            const float txc = t[0] / SCONST, tyc = t[1] / SCONST;
            const float tw = t[2], th = t[3];
            const float tx0 = txc - 0.5f * tw, ty0 = tyc - 0.5f * th;
            const float tx1 = txc + 0.5f * tw, ty1 = tyc + 0.5f * th;
            const float area_t = (tx1 - tx0) * (ty1 - ty0);

            // IoU of each pred box vs target box 0; first-occurrence argmax
            float best_iou = -1.0f;
            int   best_b   = 0;
            #pragma unroll
            for (int b = 0; b < 2; ++b) {
                const float* pb = p + 5 * b;
                const float pxc = pb[0] / SCONST, pyc = pb[1] / SCONST;
                const float pw = pb[2], ph = pb[3];
                const float px0 = pxc - 0.5f * pw, py0 = pyc - 0.5f * ph;
                const float px1 = pxc + 0.5f * pw, py1 = pyc + 0.5f * ph;
                const float iw = fmaxf(fminf(px1, tx1) - fmaxf(px0, tx0), 0.0f);
                const float ih = fmaxf(fminf(py1, ty1) - fmaxf(py0, ty0), 0.0f);
                const float inter  = iw * ih;
                const float area_p = (px1 - px0) * (py1 - py0);
                const float uni    = fmaxf(area_p + area_t - inter, 1e-10f);
                const float iou    = inter / uni;
                if (iou > best_iou) { best_iou = iou; best_b = b; }
            }

            // responsible-box coord / obj losses (target box indexed by same b)
            const float* pb = p + 5 * best_b;
            const float* tb = t + 5 * best_b;
            const float dx = pb[0] - tb[0];
            const float dy = pb[1] - tb[1];
            const float loss_xy = dx * dx + dy * dy;
            const float dw = sqrtf(pb[2]) - sqrtf(tb[2]);
            const float dh = sqrtf(pb[3]) - sqrtf(tb[3]);
            const float loss_wh = dw * dw + dh * dh;
            const float dob = pb[4] - best_iou;
            const float loss_obj = dob * dob;

            acc += (objf * (5.0f * (loss_xy + loss_wh) + loss_obj)
                    + 0.5f * loss_noobj + loss_class) * inv_bs;
        }
        s = (s + 1 >= NSTAGE) ? 0 : s + 1;
        // no second barrier: reuse distance 3 makes the next iteration's
        // wait+sync the safety point for this buffer
    }

    // ---- block reduction of per-thread accumulators ----
    float v = acc;
    #pragma unroll
    for (int o = 16; o > 0; o >>= 1) v += __shfl_down_sync(0xffffffffu, v, o);
    __shared__ float red[TPB / 32];
    __shared__ bool  isLast;
    const int warp = threadIdx.x >> 5, lane = threadIdx.x & 31;
    if (lane == 0) red[warp] = v;
    __syncthreads();
    if (warp == 0) {
        v = (lane < TPB / 32) ? red[lane] : 0.0f;
        #pragma unroll
        for (int o = 2; o > 0; o >>= 1) v += __shfl_down_sync(0xfu, v, o);
        if (lane == 0) {
            g_part[blockIdx.x] = v;
            __threadfence();
            unsigned old = atomicAdd(&g_count, 1u);
            isLast = (old == gridDim.x - 1);
        }
    }
    __syncthreads();

    // ---- last block: deterministic fixed-order sum of partials ----
    if (isLast) {
        __threadfence();   // acquire: make all g_part writes visible
        float sum = 0.0f;
        for (int i = threadIdx.x; i < (int)gridDim.x; i += TPB) sum += g_part[i];
        #pragma unroll
        for (int o = 16; o > 0; o >>= 1) sum += __shfl_down_sync(0xffffffffu, sum, o);
        if (lane == 0) red[warp] = sum;
        __syncthreads();
        if (warp == 0) {
            sum = (lane < TPB / 32) ? red[lane] : 0.0f;
            #pragma unroll
            for (int o = 2; o > 0; o >>= 1) sum += __shfl_down_sync(0xfu, sum, o);
            if (lane == 0) {
                out[0] = sum;
                g_count = 0;   // reset for next graph replay (only live block)
            }
        }
    }
}

extern "C" void kernel_launch(void* const* d_in, const int* in_sizes, int n_in,
                              void* d_out, int out_size) {
    const float* pred = (const float*)d_in[0];
    const float* tgt  = (const float*)d_in[1];
    const int n      = in_sizes[0];           // bs*S*S*30
    const int cells  = n / CH;                // bs*S*S  (divisible by 128 here)
    const int bs     = cells / 49;            // S*S = 49
    const int nTiles = (cells + TILE - 1) / TILE;

    int sms = 148;
    cudaDeviceGetAttribute(&sms, cudaDevAttrMultiProcessorCount, 0);
    int grid = sms * 2;                       // persistent: one wave, 2 CTAs/SM
    if (grid > nTiles)  grid = nTiles;
    if (grid > MAXGRID) grid = MAXGRID;

    const size_t smem = (size_t)NSTAGE * 2 * TILE_F * sizeof(float);  // 92160 B
    cudaFuncSetAttribute(yolo_loss_kernel,
                         cudaFuncAttributeMaxDynamicSharedMemorySize, (int)smem);

    yolo_loss_kernel<<<grid, TPB, smem>>>(pred, tgt, cells, nTiles,
                                          1.0f / (float)bs, (float*)d_out);
}

// round 12
// speedup vs baseline: 1.1331x; 1.1331x over previous
#include <cuda_runtime.h>

#define TPB 128
#define TILE 128                 // cells per tile (cells % 128 == 0 for this shape)
#define NSTAGE 3
#define MAXGRID 1024
#define CH 30
#define SCONST 7.0f
#define TILE_F (TILE * CH)                   // 3840 floats / tensor / tile
#define TILE_B (TILE_F * 4)                  // 15360 bytes / tensor / tile
#define STAGE_B (2 * TILE_B)                 // 30720 bytes / stage
#define SMEM_HDR 1024                        // barrier region (keeps tiles 128B-aligned)

// Persistent-kernel partials + completion counter (no device allocation allowed).
__device__ float g_part[MAXGRID];
__device__ unsigned int g_count;   // zero-init; last block resets to 0 each run

// ---- mbarrier helpers ----
__device__ __forceinline__ void mb_init(unsigned a, unsigned cnt) {
    asm volatile("mbarrier.init.shared.b64 [%0], %1;" :: "r"(a), "r"(cnt) : "memory");
}
__device__ __forceinline__ void mb_arrive(unsigned a) {
    asm volatile("mbarrier.arrive.shared.b64 _, [%0];" :: "r"(a) : "memory");
}
// acquire wait (consumers read TMA-written smem afterwards)
__device__ __forceinline__ void mb_wait_acq(unsigned a, unsigned ph) {
    asm volatile(
        "{\n\t.reg .pred P;\n\t"
        "W%=:\n\t"
        "mbarrier.try_wait.parity.acquire.cta.shared::cta.b64 P, [%0], %1, 0x989680;\n\t"
        "@P bra.uni D%=;\n\t"
        "bra.uni W%=;\n\t"
        "D%=:\n\t}"
        :: "r"(a), "r"(ph) : "memory");
}
// relaxed wait (producer: post-wait access is async-proxy TMA only)
__device__ __forceinline__ void mb_wait_rlx(unsigned a, unsigned ph) {
    asm volatile(
        "{\n\t.reg .pred P;\n\t"
        "W%=:\n\t"
        "mbarrier.try_wait.parity.relaxed.cta.shared::cta.b64 P, [%0], %1, 0x989680;\n\t"
        "@P bra.uni D%=;\n\t"
        "bra.uni W%=;\n\t"
        "D%=:\n\t}"
        :: "r"(a), "r"(ph) : "memory");
}
// stage one tile: expect_tx + two 1D bulk copies completing on `mbar`
__device__ __forceinline__ void bulk_stage(unsigned dst, const float* __restrict__ gp,
                                           const float* __restrict__ gt, unsigned mbar) {
    asm volatile("mbarrier.arrive.expect_tx.shared.b64 _, [%0], %1;"
                 :: "r"(mbar), "r"((unsigned)STAGE_B) : "memory");
    asm volatile("cp.async.bulk.shared::cluster.global.mbarrier::complete_tx::bytes "
                 "[%0], [%1], %2, [%3];"
                 :: "r"(dst), "l"(gp), "r"((unsigned)TILE_B), "r"(mbar) : "memory");
    asm volatile("cp.async.bulk.shared::cluster.global.mbarrier::complete_tx::bytes "
                 "[%0], [%1], %2, [%3];"
                 :: "r"(dst + TILE_B), "l"(gt), "r"((unsigned)TILE_B), "r"(mbar) : "memory");
}

__global__ void __launch_bounds__(TPB, 2)
yolo_loss_kernel(const float* __restrict__ pred,
                 const float* __restrict__ tgt,
                 int nTiles, float inv_bs,
                 float* __restrict__ out) {
    extern __shared__ float sm[];
    const unsigned smb = (unsigned)__cvta_generic_to_shared(sm);
    // barriers: full[s] at smb + s*8, empty[s] at smb + 24 + s*8
    // stage s data: pred at SMEM_HDR + s*STAGE_B, tgt at +TILE_B

    const int g    = gridDim.x;
    const int lane = threadIdx.x & 31;
    const int warp = threadIdx.x >> 5;

    // my tile count
    int m = 0;
    if (blockIdx.x < nTiles) m = (nTiles - 1 - blockIdx.x) / g + 1;

    if (threadIdx.x == 0) {
        #pragma unroll
        for (int s = 0; s < NSTAGE; ++s) {
            mb_init(smb + s * 8, 1);                  // full: expect_tx arrival
            mb_init(smb + 24 + s * 8, TPB / 32);      // empty: one arrive per warp
        }
    }
    __syncthreads();

    // ---- prologue: fill up to NSTAGE stages ----
    const int q = (m < NSTAGE) ? m : NSTAGE;
    if (threadIdx.x == 0) {
        for (int j = 0; j < q; ++j) {
            const size_t t = (size_t)(blockIdx.x + j * g);
            bulk_stage(smb + SMEM_HDR + j * STAGE_B,
                       pred + t * TILE_F, tgt + t * TILE_F, smb + j * 8);
        }
    }

    float acc = 0.0f;
    int cs = 0, cph = 0;            // consumer cursor
    int ps = 0, pph = 0;            // producer cursor (next refill = ring cycle 1)
    int jNext = q;

    for (int i = 0; i < m; ++i) {
        // wait this tile's data (per-thread; no block barrier)
        mb_wait_acq(smb + cs * 8, (unsigned)cph);

        // ---- compute this tile (one cell per thread) ----
        {
            const float* p = sm + (SMEM_HDR / 4) + cs * (STAGE_B / 4) + threadIdx.x * CH;
            const float* t = p + TILE_F;

            const float objf   = (t[4] > 0.0f) ? 1.0f : 0.0f;
            const float noobjf = 1.0f - objf;

            // no-object confidence loss (conf channels 4 and 9)
            const float d0 = p[4] - t[4];
            const float d1 = p[9] - t[9];
            const float loss_noobj = noobjf * (d0 * d0 + d1 * d1);

            // class loss (channels 10..29)
            float loss_class = 0.0f;
            #pragma unroll
            for (int k = 10; k < 30; ++k) {
                const float d = p[k] - t[k];
                loss_class += d * d;
            }
            loss_class *= objf;

            // target box 0 -> xyxy (match reference rounding)
            const float txc = t[0] / SCONST, tyc = t[1] / SCONST;
            const float tw = t[2], th = t[3];
            const float tx0 = txc - 0.5f * tw, ty0 = tyc - 0.5f * th;
            const float tx1 = txc + 0.5f * tw, ty1 = tyc + 0.5f * th;
            const float area_t = (tx1 - tx0) * (ty1 - ty0);

            // IoU of each pred box vs target box 0; first-occurrence argmax
            float best_iou = -1.0f;
            int   best_b   = 0;
            #pragma unroll
            for (int b = 0; b < 2; ++b) {
                const float* pb = p + 5 * b;
                const float pxc = pb[0] / SCONST, pyc = pb[1] / SCONST;
                const float pw = pb[2], ph = pb[3];
                const float px0 = pxc - 0.5f * pw, py0 = pyc - 0.5f * ph;
                const float px1 = pxc + 0.5f * pw, py1 = pyc + 0.5f * ph;
                const float iw = fmaxf(fminf(px1, tx1) - fmaxf(px0, tx0), 0.0f);
                const float ih = fmaxf(fminf(py1, ty1) - fmaxf(py0, ty0), 0.0f);
                const float inter  = iw * ih;
                const float area_p = (px1 - px0) * (py1 - py0);
                const float uni    = fmaxf(area_p + area_t - inter, 1e-10f);
                const float iou    = inter / uni;
                if (iou > best_iou) { best_iou = iou; best_b = b; }
            }

            // responsible-box coord / obj losses (target box indexed by same b)
            const float* pb = p + 5 * best_b;
            const float* tb = t + 5 * best_b;
            const float dx = pb[0] - tb[0];
            const float dy = pb[1] - tb[1];
            const float loss_xy = dx * dx + dy * dy;
            const float dw = sqrtf(pb[2]) - sqrtf(tb[2]);
            const float dh = sqrtf(pb[3]) - sqrtf(tb[3]);
            const float loss_wh = dw * dw + dh * dh;
            const float dob = pb[4] - best_iou;
            const float loss_obj = dob * dob;

            acc += (objf * (5.0f * (loss_xy + loss_wh) + loss_obj)
                    + 0.5f * loss_noobj + loss_class) * inv_bs;
        }

        // this warp is done with stage cs
        __syncwarp();
        if (lane == 0) mb_arrive(smb + 24 + cs * 8);

        // producer: refill the ring (thread 0 only; waits for all 4 warps' arrivals)
        if (threadIdx.x == 0 && jNext < m) {
            mb_wait_rlx(smb + 24 + ps * 8, (unsigned)pph);
            const size_t t = (size_t)(blockIdx.x + jNext * g);
            bulk_stage(smb + SMEM_HDR + ps * STAGE_B,
                       pred + t * TILE_F, tgt + t * TILE_F, smb + ps * 8);
            ++jNext;
            if (++ps == NSTAGE) { ps = 0; pph ^= 1; }
        }

        if (++cs == NSTAGE) { cs = 0; cph ^= 1; }
    }

    // ---- block reduction of per-thread accumulators ----
    float v = acc;
    #pragma unroll
    for (int o = 16; o > 0; o >>= 1) v += __shfl_down_sync(0xffffffffu, v, o);
    __shared__ float red[TPB / 32];
    __shared__ bool  isLast;
    if (lane == 0) red[warp] = v;
    __syncthreads();
    if (warp == 0) {
        v = (lane < TPB / 32) ? red[lane] : 0.0f;
        #pragma unroll
        for (int o = 2; o > 0; o >>= 1) v += __shfl_down_sync(0xfu, v, o);
        if (lane == 0) {
            g_part[blockIdx.x] = v;
            __threadfence();
            unsigned old = atomicAdd(&g_count, 1u);
            isLast = (old == gridDim.x - 1);
        }
    }
    __syncthreads();

    // ---- last block: deterministic fixed-order sum of partials ----
    if (isLast) {
        __threadfence();   // acquire: make all g_part writes visible
        float s = 0.0f;
        for (int i = threadIdx.x; i < (int)gridDim.x; i += TPB) s += g_part[i];
        #pragma unroll
        for (int o = 16; o > 0; o >>= 1) s += __shfl_down_sync(0xffffffffu, s, o);
        if (lane == 0) red[warp] = s;
        __syncthreads();
        if (warp == 0) {
            s = (lane < TPB / 32) ? red[lane] : 0.0f;
            #pragma unroll
            for (int o = 2; o > 0; o >>= 1) s += __shfl_down_sync(0xfu, s, o);
            if (lane == 0) {
                out[0] = s;
                g_count = 0;   // reset for next graph replay (only live block)
            }
        }
    }
}

extern "C" void kernel_launch(void* const* d_in, const int* in_sizes, int n_in,
                              void* d_out, int out_size) {
    const float* pred = (const float*)d_in[0];
    const float* tgt  = (const float*)d_in[1];
    const int n      = in_sizes[0];           // bs*S*S*30
    const int cells  = n / CH;                // bs*S*S  (divisible by 128)
    const int bs     = cells / 49;            // S*S = 49
    const int nTiles = cells / TILE;

    int sms = 148;
    cudaDeviceGetAttribute(&sms, cudaDevAttrMultiProcessorCount, 0);
    int grid = sms * 2;                       // persistent: one wave, 2 CTAs/SM
    if (grid > nTiles)  grid = nTiles;
    if (grid > MAXGRID) grid = MAXGRID;

    const size_t smem = SMEM_HDR + (size_t)NSTAGE * STAGE_B;   // 1024 + 92160 = 93184 B
    cudaFuncSetAttribute(yolo_loss_kernel,
                         cudaFuncAttributeMaxDynamicSharedMemorySize, (int)smem);

    yolo_loss_kernel<<<grid, TPB, smem>>>(pred, tgt, nTiles,
                                          1.0f / (float)bs, (float*)d_out);
}

// round 13
// speedup vs baseline: 1.1611x; 1.0247x over previous
#include <cuda_runtime.h>

#define TPB 160                  // 4 consumer warps + 1 producer warp
#define NCONS 128                // consumer threads
#define TILE 128                 // cells per tile (cells % 128 == 0 for this shape)
#define NSTAGE 3
#define MAXGRID 1024
#define CH 30
#define SCONST 7.0f
#define TILE_F (TILE * CH)                   // 3840 floats / tensor / tile
#define TILE_B (TILE_F * 4)                  // 15360 bytes / tensor / tile
#define STAGE_B (2 * TILE_B)                 // 30720 bytes / stage
#define SMEM_HDR 1024                        // barrier region (keeps tiles 128B-aligned)

// Persistent-kernel partials + completion counter (no device allocation allowed).
__device__ float g_part[MAXGRID];
__device__ unsigned int g_count;   // zero-init; last block resets to 0 each run

// ---- mbarrier helpers ----
__device__ __forceinline__ void mb_init(unsigned a, unsigned cnt) {
    asm volatile("mbarrier.init.shared.b64 [%0], %1;" :: "r"(a), "r"(cnt) : "memory");
}
__device__ __forceinline__ void mb_arrive(unsigned a) {
    asm volatile("mbarrier.arrive.shared.b64 _, [%0];" :: "r"(a) : "memory");
}
// acquire wait (consumers read TMA-written smem afterwards)
__device__ __forceinline__ void mb_wait_acq(unsigned a, unsigned ph) {
    asm volatile(
        "{\n\t.reg .pred P;\n\t"
        "W%=:\n\t"
        "mbarrier.try_wait.parity.acquire.cta.shared::cta.b64 P, [%0], %1, 0x989680;\n\t"
        "@P bra.uni D%=;\n\t"
        "bra.uni W%=;\n\t"
        "D%=:\n\t}"
        :: "r"(a), "r"(ph) : "memory");
}
// relaxed wait (producer: post-wait access is async-proxy TMA only)
__device__ __forceinline__ void mb_wait_rlx(unsigned a, unsigned ph) {
    asm volatile(
        "{\n\t.reg .pred P;\n\t"
        "W%=:\n\t"
        "mbarrier.try_wait.parity.relaxed.cta.shared::cta.b64 P, [%0], %1, 0x989680;\n\t"
        "@P bra.uni D%=;\n\t"
        "bra.uni W%=;\n\t"
        "D%=:\n\t}"
        :: "r"(a), "r"(ph) : "memory");
}
// stage one tile: expect_tx + two 1D bulk copies completing on `mbar`
__device__ __forceinline__ void bulk_stage(unsigned dst, const float* __restrict__ gp,
                                           const float* __restrict__ gt, unsigned mbar) {
    asm volatile("mbarrier.arrive.expect_tx.shared.b64 _, [%0], %1;"
                 :: "r"(mbar), "r"((unsigned)STAGE_B) : "memory");
    asm volatile("cp.async.bulk.shared::cluster.global.mbarrier::complete_tx::bytes "
                 "[%0], [%1], %2, [%3];"
                 :: "r"(dst), "l"(gp), "r"((unsigned)TILE_B), "r"(mbar) : "memory");
    asm volatile("cp.async.bulk.shared::cluster.global.mbarrier::complete_tx::bytes "
                 "[%0], [%1], %2, [%3];"
                 :: "r"(dst + TILE_B), "l"(gt), "r"((unsigned)TILE_B), "r"(mbar) : "memory");
}

__global__ void __launch_bounds__(TPB, 2)
yolo_loss_kernel(const float* __restrict__ pred,
                 const float* __restrict__ tgt,
                 int nTiles, float inv_bs,
                 float* __restrict__ out) {
    extern __shared__ float sm[];
    const unsigned smb = (unsigned)__cvta_generic_to_shared(sm);
    // barriers: full[s] at smb + s*8, empty[s] at smb + 24 + s*8
    // stage s data: pred at SMEM_HDR + s*STAGE_B, tgt at +TILE_B

    const int g    = gridDim.x;
    const int lane = threadIdx.x & 31;
    const int warp = threadIdx.x >> 5;

    // my tile count
    int m = 0;
    if (blockIdx.x < nTiles) m = (nTiles - 1 - blockIdx.x) / g + 1;
    const int q = (m < NSTAGE) ? m : NSTAGE;

    if (threadIdx.x == 0) {
        #pragma unroll
        for (int s = 0; s < NSTAGE; ++s) {
            mb_init(smb + s * 8, 1);                  // full: expect_tx arrival
            mb_init(smb + 24 + s * 8, NCONS / 32);    // empty: one arrive per consumer warp
        }
    }
    __syncthreads();

    float acc = 0.0f;

    if (warp == 4) {
        // ================= producer warp (lane 0 only) =================
        if (lane == 0) {
            // prologue: fill up to NSTAGE stages
            for (int j = 0; j < q; ++j) {
                const size_t t = (size_t)(blockIdx.x + j * g);
                bulk_stage(smb + SMEM_HDR + j * STAGE_B,
                           pred + t * TILE_F, tgt + t * TILE_F, smb + j * 8);
            }
            // steady state: refill as soon as a stage drains
            int ps = 0, pph = 0;
            for (int j = q; j < m; ++j) {
                mb_wait_rlx(smb + 24 + ps * 8, (unsigned)pph);
                const size_t t = (size_t)(blockIdx.x + j * g);
                bulk_stage(smb + SMEM_HDR + ps * STAGE_B,
                           pred + t * TILE_F, tgt + t * TILE_F, smb + ps * 8);
                if (++ps == NSTAGE) { ps = 0; pph ^= 1; }
            }
        }
    } else {
        // ================= consumer warps 0..3 =================
        int cs = 0, cph = 0;
        for (int i = 0; i < m; ++i) {
            mb_wait_acq(smb + cs * 8, (unsigned)cph);

            const float* p = sm + (SMEM_HDR / 4) + cs * (STAGE_B / 4) + threadIdx.x * CH;
            const float* t = p + TILE_F;

            const float objf   = (t[4] > 0.0f) ? 1.0f : 0.0f;
            const float noobjf = 1.0f - objf;

            // no-object confidence loss (conf channels 4 and 9)
            const float d0 = p[4] - t[4];
            const float d1 = p[9] - t[9];
            const float loss_noobj = noobjf * (d0 * d0 + d1 * d1);

            // class loss (channels 10..29)
            float loss_class = 0.0f;
            #pragma unroll
            for (int k = 10; k < 30; ++k) {
                const float d = p[k] - t[k];
                loss_class += d * d;
            }
            loss_class *= objf;

            // target box 0 -> xyxy (match reference rounding)
            const float txc = t[0] / SCONST, tyc = t[1] / SCONST;
            const float tw = t[2], th = t[3];
            const float tx0 = txc - 0.5f * tw, ty0 = tyc - 0.5f * th;
            const float tx1 = txc + 0.5f * tw, ty1 = tyc + 0.5f * th;
            const float area_t = (tx1 - tx0) * (ty1 - ty0);

            // IoU of each pred box vs target box 0; first-occurrence argmax
            float best_iou = -1.0f;
            int   best_b   = 0;
            #pragma unroll
            for (int b = 0; b < 2; ++b) {
                const float* pb = p + 5 * b;
                const float pxc = pb[0] / SCONST, pyc = pb[1] / SCONST;
                const float pw = pb[2], ph = pb[3];
                const float px0 = pxc - 0.5f * pw, py0 = pyc - 0.5f * ph;
                const float px1 = pxc + 0.5f * pw, py1 = pyc + 0.5f * ph;
                const float iw = fmaxf(fminf(px1, tx1) - fmaxf(px0, tx0), 0.0f);
                const float ih = fmaxf(fminf(py1, ty1) - fmaxf(py0, ty0), 0.0f);
                const float inter  = iw * ih;
                const float area_p = (px1 - px0) * (py1 - py0);
                const float uni    = fmaxf(area_p + area_t - inter, 1e-10f);
                const float iou    = inter / uni;
                if (iou > best_iou) { best_iou = iou; best_b = b; }
            }

            // responsible-box coord / obj losses (target box indexed by same b)
            const float* pb = p + 5 * best_b;
            const float* tb = t + 5 * best_b;
            const float dx = pb[0] - tb[0];
            const float dy = pb[1] - tb[1];
            const float loss_xy = dx * dx + dy * dy;
            const float dw = sqrtf(pb[2]) - sqrtf(tb[2]);
            const float dh = sqrtf(pb[3]) - sqrtf(tb[3]);
            const float loss_wh = dw * dw + dh * dh;
            const float dob = pb[4] - best_iou;
            const float loss_obj = dob * dob;

            acc += (objf * (5.0f * (loss_xy + loss_wh) + loss_obj)
                    + 0.5f * loss_noobj + loss_class) * inv_bs;

            // this warp is done with stage cs
            __syncwarp();
            if (lane == 0) mb_arrive(smb + 24 + cs * 8);

            if (++cs == NSTAGE) { cs = 0; cph ^= 1; }
        }
    }

    // ---- block reduction of per-thread accumulators (producer contributes 0) ----
    float v = acc;
    #pragma unroll
    for (int o = 16; o > 0; o >>= 1) v += __shfl_down_sync(0xffffffffu, v, o);
    __shared__ float red[TPB / 32];
    __shared__ bool  isLast;
    if (lane == 0) red[warp] = v;
    __syncthreads();
    if (warp == 0) {
        v = (lane < TPB / 32) ? red[lane] : 0.0f;
        #pragma unroll
        for (int o = 4; o > 0; o >>= 1) v += __shfl_down_sync(0xffu, v, o);
        if (lane == 0) {
            g_part[blockIdx.x] = v;
            __threadfence();
            unsigned old = atomicAdd(&g_count, 1u);
            isLast = (old == gridDim.x - 1);
        }
    }
    __syncthreads();

    // ---- last block: deterministic fixed-order sum of partials ----
    if (isLast) {
        __threadfence();   // acquire: make all g_part writes visible
        float s = 0.0f;
        for (int i = threadIdx.x; i < (int)gridDim.x; i += TPB) s += g_part[i];
        #pragma unroll
        for (int o = 16; o > 0; o >>= 1) s += __shfl_down_sync(0xffffffffu, s, o);
        if (lane == 0) red[warp] = s;
        __syncthreads();
        if (warp == 0) {
            s = (lane < TPB / 32) ? red[lane] : 0.0f;
            #pragma unroll
            for (int o = 4; o > 0; o >>= 1) s += __shfl_down_sync(0xffu, s, o);
            if (lane == 0) {
                out[0] = s;
                g_count = 0;   // reset for next graph replay (only live block)
            }
        }
    }
}

extern "C" void kernel_launch(void* const* d_in, const int* in_sizes, int n_in,
                              void* d_out, int out_size) {
    const float* pred = (const float*)d_in[0];
    const float* tgt  = (const float*)d_in[1];
    const int n      = in_sizes[0];           // bs*S*S*30
    const int cells  = n / CH;                // bs*S*S  (divisible by 128)
    const int bs     = cells / 49;            // S*S = 49
    const int nTiles = cells / TILE;

    int sms = 148;
    cudaDeviceGetAttribute(&sms, cudaDevAttrMultiProcessorCount, 0);
    int grid = sms * 2;                       // persistent: one wave, 2 CTAs/SM
    if (grid > nTiles)  grid = nTiles;
    if (grid > MAXGRID) grid = MAXGRID;

    const size_t smem = SMEM_HDR + (size_t)NSTAGE * STAGE_B;   // 1024 + 92160 = 93184 B
    cudaFuncSetAttribute(yolo_loss_kernel,
                         cudaFuncAttributeMaxDynamicSharedMemorySize, (int)smem);

    yolo_loss_kernel<<<grid, TPB, smem>>>(pred, tgt, nTiles,
                                          1.0f / (float)bs, (float*)d_out);
}